// round 9
// baseline (speedup 1.0000x reference)
#include <cuda_runtime.h>
#include <math.h>
#include <stdint.h>

#define C 256
#define B 16
#define TILE 24              // rows per smem tile (24 KB) -> 3 rows/warp
#define DEPTH 3              // pipeline stages
#define THREADS 256          // 8 warps per block
#define NBLOCKS 444          // 3 per SM

#define TILE_FLOATS (TILE * C)
#define SMEM_BYTES (DEPTH * TILE_FLOATS * 4 + DEPTH * 8 + 8)

// Scratch accumulators (device globals; re-zeroed by the folding CTA each replay)
__device__ float g_S1[B * C];
__device__ float g_S2[B * C];
__device__ float g_Z[B];
__device__ float g_W[B];
__device__ float g_mean[C];
__device__ float g_rstd[C];
__device__ unsigned int g_ctr;   // last-block ticket (reset by folding CTA)

// ---------------------------------------------------------------------------
// PTX helpers
// ---------------------------------------------------------------------------
__device__ __forceinline__ uint32_t smem_u32(const void* p) {
    uint32_t a;
    asm("{ .reg .u64 t; cvta.to.shared.u64 t, %1; cvt.u32.u64 %0, t; }"
        : "=r"(a) : "l"(p));
    return a;
}
__device__ __forceinline__ void mbar_init(uint32_t mbar, uint32_t cnt) {
    asm volatile("mbarrier.init.shared.b64 [%0], %1;" :: "r"(mbar), "r"(cnt) : "memory");
}
__device__ __forceinline__ void mbar_expect_tx(uint32_t mbar, uint32_t bytes) {
    asm volatile("mbarrier.arrive.expect_tx.shared.b64 _, [%0], %1;"
                 :: "r"(mbar), "r"(bytes) : "memory");
}
__device__ __forceinline__ void bulk_g2s(uint32_t dst, const void* src,
                                         uint32_t bytes, uint32_t mbar) {
    asm volatile(
        "cp.async.bulk.shared::cta.global.mbarrier::complete_tx::bytes [%0], [%1], %2, [%3];"
        :: "r"(dst), "l"(src), "r"(bytes), "r"(mbar) : "memory");
}
__device__ __forceinline__ void mbar_wait(uint32_t mbar, uint32_t parity) {
    uint32_t done;
    asm volatile(
        "{\n\t.reg .pred p;\n\t"
        "mbarrier.try_wait.parity.acquire.cta.shared::cta.b64 p, [%1], %2;\n\t"
        "selp.b32 %0, 1, 0, p;\n\t}"
        : "=r"(done) : "r"(mbar), "r"(parity) : "memory");
    if (!done) {
        asm volatile(
            "{\n\t.reg .pred P1;\n\t"
            "W_%=:\n\t"
            "mbarrier.try_wait.parity.acquire.cta.shared::cta.b64 P1, [%0], %1, 0x989680;\n\t"
            "@P1 bra.uni D_%=;\n\t"
            "bra.uni W_%=;\n\t"
            "D_%=:\n\t}"
            :: "r"(mbar), "r"(parity) : "memory");
    }
}

// ---------------------------------------------------------------------------
__device__ __forceinline__ void flush_acc(int segv, int lane,
                                          float* s1, float* s2,
                                          float zacc, float wacc) {
    int c0 = lane * 4;
    int c1 = 128 + lane * 4;
#pragma unroll
    for (int k = 0; k < 4; k++) {
        atomicAdd(&g_S1[segv * C + c0 + k], s1[k]);
        atomicAdd(&g_S1[segv * C + c1 + k], s1[4 + k]);
        atomicAdd(&g_S2[segv * C + c0 + k], s2[k]);
        atomicAdd(&g_S2[segv * C + c1 + k], s2[4 + k]);
    }
    if (lane == 0) {
        atomicAdd(&g_Z[segv], zacc);
        atomicAdd(&g_W[segv], wacc);
    }
}

#define DOT8(x0, x1, w0, w1) \
    (x0.x*w0.x + x0.y*w0.y + x0.z*w0.z + x0.w*w0.w + \
     x1.x*w1.x + x1.y*w1.y + x1.z*w1.z + x1.w*w1.w)

__device__ __forceinline__ void accum_row(float wr, float4 x0, float4 x1,
                                          float* s1, float* s2) {
    float t;
    t = wr * x0.x; s1[0] += t; s2[0] += t * x0.x;
    t = wr * x0.y; s1[1] += t; s2[1] += t * x0.y;
    t = wr * x0.z; s1[2] += t; s2[2] += t * x0.z;
    t = wr * x0.w; s1[3] += t; s2[3] += t * x0.w;
    t = wr * x1.x; s1[4] += t; s2[4] += t * x1.x;
    t = wr * x1.y; s1[5] += t; s2[5] += t * x1.y;
    t = wr * x1.z; s1[6] += t; s2[6] += t * x1.z;
    t = wr * x1.w; s1[7] += t; s2[7] += t * x1.w;
}

// ---------------------------------------------------------------------------
// pass 1: TMA bulk-copy pipeline into smem ring; 8 warps, 3 rows/warp/tile.
// The last CTA to finish folds the B-segment accumulators into mean/rstd
// (replaces the separate finalize kernel) and re-zeros for the next replay.
// ---------------------------------------------------------------------------
extern __shared__ char smem_raw[];

__global__ __launch_bounds__(THREADS, 3)
void pass1_kernel(const float* __restrict__ feats,
                  const int*   __restrict__ seg,
                  const float* __restrict__ wl,
                  const float* __restrict__ bl,
                  const float* __restrict__ wg,
                  const float* __restrict__ bg,
                  int n)
{
    __shared__ float4 swl[64];
    __shared__ float4 swg[64];
    __shared__ unsigned int rank_s;
    __shared__ float invZ[B];
    __shared__ float invU;

    float* tiles = (float*)smem_raw;
    uint64_t* mbar64 = (uint64_t*)(smem_raw + (size_t)DEPTH * TILE_FLOATS * 4);

    int ntiles = (n + TILE - 1) / TILE;
    int chunk  = (ntiles + NBLOCKS - 1) / NBLOCKS;
    int t0 = blockIdx.x * chunk;
    int t1 = min(ntiles, t0 + chunk);
    int nt = t1 - t0;

    int tid  = threadIdx.x;
    int warp = tid >> 5;
    int lane = tid & 31;

    if (nt > 0) {
        uint32_t mb[DEPTH];
#pragma unroll
        for (int d = 0; d < DEPTH; d++) mb[d] = smem_u32(&mbar64[d]);
        uint32_t tile_s[DEPTH];
#pragma unroll
        for (int d = 0; d < DEPTH; d++) tile_s[d] = smem_u32(tiles + d * TILE_FLOATS);

        // preload weights into smem
        if (tid < 64)        swl[tid]      = ((const float4*)wl)[tid];
        else if (tid < 128)  swg[tid - 64] = ((const float4*)wg)[tid - 64];

        if (tid == 0) {
#pragma unroll
            for (int d = 0; d < DEPTH; d++) mbar_init(mb[d], 1);
        }
        __syncthreads();

        if (tid == 0) {
            int pre = min(DEPTH, nt);
            for (int i = 0; i < pre; i++) {
                int t = t0 + i;
                int rows = min(TILE, n - t * TILE);
                uint32_t bytes = (uint32_t)rows * C * 4;
                mbar_expect_tx(mb[i], bytes);
                bulk_g2s(tile_s[i], feats + (size_t)t * TILE_FLOATS, bytes, mb[i]);
            }
        }

        float blv = bl[0], bgv = bg[0];

        float s1[8], s2[8];
#pragma unroll
        for (int k = 0; k < 8; k++) { s1[k] = 0.f; s2[k] = 0.f; }
        float zacc = 0.f, wacc = 0.f;
        int cur = __ldg(&seg[min(n - 1, t0 * TILE + warp * 3)]);

        for (int i = 0; i < nt; i++) {
            int st = i % DEPTH;
            uint32_t parity = (uint32_t)((i / DEPTH) & 1);
            mbar_wait(mb[st], parity);

            const float* tp = tiles + st * TILE_FLOATS;
            int base = (t0 + i) * TILE;
            int rows = min(TILE, n - base);

            int s_lo = __ldg(&seg[base]);
            int s_hi = __ldg(&seg[base + rows - 1]);

            float4 wl0 = swl[lane], wl1 = swl[32 + lane];
            float4 wg0 = swg[lane], wg1 = swg[32 + lane];

            if (s_lo == s_hi && rows == TILE) {
                // ---- fast path: whole tile one segment; warp handles 3 rows ----
                if (s_lo != cur) {
                    flush_acc(cur, lane, s1, s2, zacc, wacc);
#pragma unroll
                    for (int k = 0; k < 8; k++) { s1[k] = 0.f; s2[k] = 0.f; }
                    zacc = 0.f; wacc = 0.f;
                    cur = s_lo;
                }
                const float* rp = tp + (warp * 3) * C + lane * 4;
                float4 xa0 = *(const float4*)(rp);
                float4 xa1 = *(const float4*)(rp + 128);
                float4 xb0 = *(const float4*)(rp + C);
                float4 xb1 = *(const float4*)(rp + C + 128);
                float4 xc0 = *(const float4*)(rp + 2 * C);
                float4 xc1 = *(const float4*)(rp + 2 * C + 128);

                float dla = DOT8(xa0, xa1, wl0, wl1), dga = DOT8(xa0, xa1, wg0, wg1);
                float dlb = DOT8(xb0, xb1, wl0, wl1), dgb = DOT8(xb0, xb1, wg0, wg1);
                float dlc = DOT8(xc0, xc1, wl0, wl1), dgc = DOT8(xc0, xc1, wg0, wg1);

                // 6 interleaved butterfly chains
#pragma unroll
                for (int o = 16; o; o >>= 1) {
                    dla += __shfl_xor_sync(0xffffffffu, dla, o);
                    dga += __shfl_xor_sync(0xffffffffu, dga, o);
                    dlb += __shfl_xor_sync(0xffffffffu, dlb, o);
                    dgb += __shfl_xor_sync(0xffffffffu, dgb, o);
                    dlc += __shfl_xor_sync(0xffffffffu, dlc, o);
                    dgc += __shfl_xor_sync(0xffffffffu, dgc, o);
                }
                float ea = __expf(dga + bgv);
                float eb = __expf(dgb + bgv);
                float ec = __expf(dgc + bgv);
                float wra = __fdividef(ea, 1.0f + __expf(-(dla + blv)));
                float wrb = __fdividef(eb, 1.0f + __expf(-(dlb + blv)));
                float wrc = __fdividef(ec, 1.0f + __expf(-(dlc + blv)));
                zacc += ea + eb + ec;
                wacc += wra + wrb + wrc;
                accum_row(wra, xa0, xa1, s1, s2);
                accum_row(wrb, xb0, xb1, s1, s2);
                accum_row(wrc, xc0, xc1, s1, s2);
            } else {
                // ---- slow path: boundary/partial tile ----
#pragma unroll
                for (int j = 0; j < 3; j++) {
                    int lr = warp * 3 + j;
                    if (lr < rows) {
                        int sv = __ldg(&seg[base + lr]);
                        if (sv != cur) {
                            flush_acc(cur, lane, s1, s2, zacc, wacc);
#pragma unroll
                            for (int k = 0; k < 8; k++) { s1[k] = 0.f; s2[k] = 0.f; }
                            zacc = 0.f; wacc = 0.f;
                            cur = sv;
                        }
                        float4 x0 = *(const float4*)(tp + lr * C + lane * 4);
                        float4 x1 = *(const float4*)(tp + lr * C + 128 + lane * 4);
                        float dl = DOT8(x0, x1, wl0, wl1);
                        float dg = DOT8(x0, x1, wg0, wg1);
#pragma unroll
                        for (int o = 16; o; o >>= 1) {
                            dl += __shfl_xor_sync(0xffffffffu, dl, o);
                            dg += __shfl_xor_sync(0xffffffffu, dg, o);
                        }
                        float e  = __expf(dg + bgv);
                        float wr = __fdividef(e, 1.0f + __expf(-(dl + blv)));
                        zacc += e;
                        wacc += wr;
                        accum_row(wr, x0, x1, s1, s2);
                    }
                }
            }

            __syncthreads();   // all warps done with stage st
            if (tid == 0 && i + DEPTH < nt) {
                int t = t0 + i + DEPTH;
                int rows2 = min(TILE, n - t * TILE);
                uint32_t bytes = (uint32_t)rows2 * C * 4;
                mbar_expect_tx(mb[st], bytes);
                bulk_g2s(tile_s[st], feats + (size_t)t * TILE_FLOATS, bytes, mb[st]);
            }
        }
        flush_acc(cur, lane, s1, s2, zacc, wacc);
    }

    // -------- last-block fold (replaces finalize kernel) --------
    __threadfence();                       // make this CTA's atomics visible
    if (tid == 0) rank_s = atomicAdd(&g_ctr, 1u);
    __syncthreads();
    if (rank_s == NBLOCKS - 1) {
        __threadfence();                   // see all other CTAs' atomics
        int t = tid;                       // 0..255 == channel
        if (t < B) invZ[t] = 1.0f / g_Z[t];
        __syncthreads();
        if (t == 0) {
            float U = 0.f;
            for (int b = 0; b < B; b++) U += g_W[b] * invZ[b];
            invU = 1.0f / U;
            g_ctr = 0;                     // reset ticket for next replay
        }
        __syncthreads();
        float m1 = 0.f, m2 = 0.f;
        for (int b = 0; b < B; b++) {
            m1 += g_S1[b * C + t] * invZ[b];
            m2 += g_S2[b * C + t] * invZ[b];
        }
        float iu = invU;
        m1 *= iu;
        m2 *= iu;
        float var = m2 - m1 * m1;          // sum(weight) == 1 exactly in the math
        g_mean[t] = m1;
        g_rstd[t] = 1.0f / sqrtf(var);
        // re-zero accumulators for next replay
        for (int b = 0; b < B; b++) {
            g_S1[b * C + t] = 0.f;
            g_S2[b * C + t] = 0.f;
        }
        if (t < B) { g_Z[t] = 0.f; g_W[t] = 0.f; }
    }
}

// ---------------------------------------------------------------------------
// pass 2: out = (x - mean[c]) * rstd[c]
// ---------------------------------------------------------------------------
__global__ __launch_bounds__(256)
void normalize_kernel(const float* __restrict__ feats,
                      float* __restrict__ out, int total4)
{
    int base = blockIdx.x * 1024 + threadIdx.x;
    if (base >= total4) return;
    const float4* f4 = (const float4*)feats;
    float4*       o4 = (float4*)out;
    const float4* m4 = (const float4*)g_mean;
    const float4* r4 = (const float4*)g_rstd;

    int cf = base & 63;
    float4 m  = m4[cf];
    float4 rs = r4[cf];

#pragma unroll
    for (int k = 0; k < 4; k++) {
        int i = base + k * 256;
        if (i < total4) {
            float4 x = __ldcs(f4 + i);
            float4 y;
            y.x = (x.x - m.x) * rs.x;
            y.y = (x.y - m.y) * rs.y;
            y.z = (x.z - m.z) * rs.z;
            y.w = (x.w - m.w) * rs.w;
            __stcs(o4 + i, y);
        }
    }
}

// ---------------------------------------------------------------------------
extern "C" void kernel_launch(void* const* d_in, const int* in_sizes, int n_in,
                              void* d_out, int out_size) {
    const float* feats = (const float*)d_in[0];
    const int*   seg   = (const int*)  d_in[1];
    const float* wl    = (const float*)d_in[2];
    const float* bl    = (const float*)d_in[3];
    const float* wg    = (const float*)d_in[4];
    const float* bg    = (const float*)d_in[5];
    float*       out   = (float*)d_out;

    int n = in_sizes[0] / C;

    cudaFuncSetAttribute(pass1_kernel,
                         cudaFuncAttributeMaxDynamicSharedMemorySize, SMEM_BYTES);

    pass1_kernel<<<NBLOCKS, THREADS, SMEM_BYTES>>>(feats, seg, wl, bl, wg, bg, n);

    int total4 = n * (C / 4);
    normalize_kernel<<<(total4 + 1023) / 1024, 256>>>(feats, out, total4);
}

// round 10
// speedup vs baseline: 1.0399x; 1.0399x over previous
#include <cuda_runtime.h>
#include <math.h>
#include <stdint.h>

#define C 256
#define B 16
#define TILE 24              // rows per smem tile (24 KB) -> 3 rows/warp
#define DEPTH 3              // pipeline stages
#define THREADS 256          // 8 warps per block
#define NBLOCKS 444          // 3 per SM

#define TILE_FLOATS (TILE * C)
#define SMEM_BYTES (DEPTH * TILE_FLOATS * 4 + DEPTH * 8 + 8)

typedef unsigned long long u64t;

// Scratch accumulators (device globals; re-zeroed in finalize each replay)
__device__ float g_S1[B * C];
__device__ float g_S2[B * C];
__device__ float g_Z[B];
__device__ float g_W[B];
__device__ float g_mean[C];
__device__ float g_rstd[C];

// ---------------------------------------------------------------------------
// PTX helpers
// ---------------------------------------------------------------------------
__device__ __forceinline__ uint32_t smem_u32(const void* p) {
    uint32_t a;
    asm("{ .reg .u64 t; cvta.to.shared.u64 t, %1; cvt.u32.u64 %0, t; }"
        : "=r"(a) : "l"(p));
    return a;
}
__device__ __forceinline__ void mbar_init(uint32_t mbar, uint32_t cnt) {
    asm volatile("mbarrier.init.shared.b64 [%0], %1;" :: "r"(mbar), "r"(cnt) : "memory");
}
__device__ __forceinline__ void mbar_expect_tx(uint32_t mbar, uint32_t bytes) {
    asm volatile("mbarrier.arrive.expect_tx.shared.b64 _, [%0], %1;"
                 :: "r"(mbar), "r"(bytes) : "memory");
}
__device__ __forceinline__ void bulk_g2s(uint32_t dst, const void* src,
                                         uint32_t bytes, uint32_t mbar) {
    asm volatile(
        "cp.async.bulk.shared::cta.global.mbarrier::complete_tx::bytes [%0], [%1], %2, [%3];"
        :: "r"(dst), "l"(src), "r"(bytes), "r"(mbar) : "memory");
}
__device__ __forceinline__ void mbar_wait(uint32_t mbar, uint32_t parity) {
    uint32_t done;
    asm volatile(
        "{\n\t.reg .pred p;\n\t"
        "mbarrier.try_wait.parity.acquire.cta.shared::cta.b64 p, [%1], %2;\n\t"
        "selp.b32 %0, 1, 0, p;\n\t}"
        : "=r"(done) : "r"(mbar), "r"(parity) : "memory");
    if (!done) {
        asm volatile(
            "{\n\t.reg .pred P1;\n\t"
            "W_%=:\n\t"
            "mbarrier.try_wait.parity.acquire.cta.shared::cta.b64 P1, [%0], %1, 0x989680;\n\t"
            "@P1 bra.uni D_%=;\n\t"
            "bra.uni W_%=;\n\t"
            "D_%=:\n\t}"
            :: "r"(mbar), "r"(parity) : "memory");
    }
}

// ---- packed f32x2 math (validated R6: rel_err 1e-7) -----------------------
__device__ __forceinline__ u64t fma2(u64t a, u64t b, u64t c) {
    u64t d;
    asm("fma.rn.f32x2 %0, %1, %2, %3;" : "=l"(d) : "l"(a), "l"(b), "l"(c));
    return d;
}
__device__ __forceinline__ u64t mul2(u64t a, u64t b) {
    u64t d;
    asm("mul.rn.f32x2 %0, %1, %2;" : "=l"(d) : "l"(a), "l"(b));
    return d;
}
__device__ __forceinline__ u64t pk2(float lo, float hi) {
    u64t r;
    asm("mov.b64 %0, {%1, %2};" : "=l"(r) : "f"(lo), "f"(hi));
    return r;
}
__device__ __forceinline__ float2 upk2(u64t v) {
    float2 f;
    asm("mov.b64 {%0, %1}, %2;" : "=f"(f.x), "=f"(f.y) : "l"(v));
    return f;
}

// ---------------------------------------------------------------------------
// flush: lane owns channels lane*4..+3 (s1p[0..1]) and 128+lane*4..+3 (s1p[2..3])
// ---------------------------------------------------------------------------
__device__ __forceinline__ void flush_acc(int segv, int lane,
                                          u64t* s1p, u64t* s2p,
                                          float zacc, float wacc) {
    int c0 = lane * 4;
    int c1 = 128 + lane * 4;
    float2 v;
    v = upk2(s1p[0]); atomicAdd(&g_S1[segv*C + c0    ], v.x); atomicAdd(&g_S1[segv*C + c0 + 1], v.y);
    v = upk2(s1p[1]); atomicAdd(&g_S1[segv*C + c0 + 2], v.x); atomicAdd(&g_S1[segv*C + c0 + 3], v.y);
    v = upk2(s1p[2]); atomicAdd(&g_S1[segv*C + c1    ], v.x); atomicAdd(&g_S1[segv*C + c1 + 1], v.y);
    v = upk2(s1p[3]); atomicAdd(&g_S1[segv*C + c1 + 2], v.x); atomicAdd(&g_S1[segv*C + c1 + 3], v.y);
    v = upk2(s2p[0]); atomicAdd(&g_S2[segv*C + c0    ], v.x); atomicAdd(&g_S2[segv*C + c0 + 1], v.y);
    v = upk2(s2p[1]); atomicAdd(&g_S2[segv*C + c0 + 2], v.x); atomicAdd(&g_S2[segv*C + c0 + 3], v.y);
    v = upk2(s2p[2]); atomicAdd(&g_S2[segv*C + c1    ], v.x); atomicAdd(&g_S2[segv*C + c1 + 1], v.y);
    v = upk2(s2p[3]); atomicAdd(&g_S2[segv*C + c1 + 2], v.x); atomicAdd(&g_S2[segv*C + c1 + 3], v.y);
    if (lane == 0) {
        atomicAdd(&g_Z[segv], zacc);
        atomicAdd(&g_W[segv], wacc);
    }
}

// packed dot: 8 channels (4 pairs), two 2-deep chains for ILP
__device__ __forceinline__ float dot_pk(ulonglong2 a0, ulonglong2 a1,
                                        ulonglong2 w0, ulonglong2 w1) {
    u64t p = fma2(a0.x, w0.x, mul2(a0.y, w0.y));
    u64t q = fma2(a1.x, w1.x, mul2(a1.y, w1.y));
    float2 fp = upk2(p), fq = upk2(q);
    return (fp.x + fq.x) + (fp.y + fq.y);
}
// packed moment accumulation for one row (8 channels)
__device__ __forceinline__ void accum_pk(float wr, ulonglong2 a0, ulonglong2 a1,
                                         u64t* s1p, u64t* s2p) {
    u64t wr2 = pk2(wr, wr);
    s1p[0] = fma2(wr2, a0.x, s1p[0]);
    s1p[1] = fma2(wr2, a0.y, s1p[1]);
    s1p[2] = fma2(wr2, a1.x, s1p[2]);
    s1p[3] = fma2(wr2, a1.y, s1p[3]);
    s2p[0] = fma2(wr2, mul2(a0.x, a0.x), s2p[0]);
    s2p[1] = fma2(wr2, mul2(a0.y, a0.y), s2p[1]);
    s2p[2] = fma2(wr2, mul2(a1.x, a1.x), s2p[2]);
    s2p[3] = fma2(wr2, mul2(a1.y, a1.y), s2p[3]);
}

// ---------------------------------------------------------------------------
// pass 1: TMA bulk-copy pipeline into smem ring; 8 warps, 3 rows/warp/tile.
// R8 geometry + f32x2 packed math for dots/moments.
// ---------------------------------------------------------------------------
extern __shared__ char smem_raw[];

__global__ __launch_bounds__(THREADS, 3)
void pass1_kernel(const float* __restrict__ feats,
                  const int*   __restrict__ seg,
                  const float* __restrict__ wl,
                  const float* __restrict__ bl,
                  const float* __restrict__ wg,
                  const float* __restrict__ bg,
                  int n)
{
    __shared__ float4 swl[64];
    __shared__ float4 swg[64];

    float* tiles = (float*)smem_raw;
    uint64_t* mbar64 = (uint64_t*)(smem_raw + (size_t)DEPTH * TILE_FLOATS * 4);

    int ntiles = (n + TILE - 1) / TILE;
    int chunk  = (ntiles + NBLOCKS - 1) / NBLOCKS;
    int t0 = blockIdx.x * chunk;
    int t1 = min(ntiles, t0 + chunk);
    int nt = t1 - t0;
    if (nt <= 0) return;

    int tid  = threadIdx.x;
    int warp = tid >> 5;
    int lane = tid & 31;

    uint32_t mb[DEPTH];
#pragma unroll
    for (int d = 0; d < DEPTH; d++) mb[d] = smem_u32(&mbar64[d]);
    uint32_t tile_s[DEPTH];
#pragma unroll
    for (int d = 0; d < DEPTH; d++) tile_s[d] = smem_u32(tiles + d * TILE_FLOATS);

    // preload weights into smem
    if (tid < 64)        swl[tid]      = ((const float4*)wl)[tid];
    else if (tid < 128)  swg[tid - 64] = ((const float4*)wg)[tid - 64];

    if (tid == 0) {
#pragma unroll
        for (int d = 0; d < DEPTH; d++) mbar_init(mb[d], 1);
    }
    __syncthreads();

    if (tid == 0) {
        int pre = min(DEPTH, nt);
        for (int i = 0; i < pre; i++) {
            int t = t0 + i;
            int rows = min(TILE, n - t * TILE);
            uint32_t bytes = (uint32_t)rows * C * 4;
            mbar_expect_tx(mb[i], bytes);
            bulk_g2s(tile_s[i], feats + (size_t)t * TILE_FLOATS, bytes, mb[i]);
        }
    }

    float blv = bl[0], bgv = bg[0];

    u64t s1p[4], s2p[4];
#pragma unroll
    for (int k = 0; k < 4; k++) { s1p[k] = 0ull; s2p[k] = 0ull; }
    float zacc = 0.f, wacc = 0.f;
    int cur = __ldg(&seg[min(n - 1, t0 * TILE + warp * 3)]);

    for (int i = 0; i < nt; i++) {
        int st = i % DEPTH;
        uint32_t parity = (uint32_t)((i / DEPTH) & 1);
        mbar_wait(mb[st], parity);

        const float* tp = tiles + st * TILE_FLOATS;
        int base = (t0 + i) * TILE;
        int rows = min(TILE, n - base);

        int s_lo = __ldg(&seg[base]);
        int s_hi = __ldg(&seg[base + rows - 1]);

        ulonglong2 wl0 = *(const ulonglong2*)&swl[lane];
        ulonglong2 wl1 = *(const ulonglong2*)&swl[32 + lane];
        ulonglong2 wg0 = *(const ulonglong2*)&swg[lane];
        ulonglong2 wg1 = *(const ulonglong2*)&swg[32 + lane];

        if (s_lo == s_hi && rows == TILE) {
            // ---- fast path: whole tile one segment; warp handles 3 rows ----
            if (s_lo != cur) {
                flush_acc(cur, lane, s1p, s2p, zacc, wacc);
#pragma unroll
                for (int k = 0; k < 4; k++) { s1p[k] = 0ull; s2p[k] = 0ull; }
                zacc = 0.f; wacc = 0.f;
                cur = s_lo;
            }
            const float* rp = tp + (warp * 3) * C + lane * 4;
            ulonglong2 xa0 = *(const ulonglong2*)(rp);
            ulonglong2 xa1 = *(const ulonglong2*)(rp + 128);
            ulonglong2 xb0 = *(const ulonglong2*)(rp + C);
            ulonglong2 xb1 = *(const ulonglong2*)(rp + C + 128);
            ulonglong2 xc0 = *(const ulonglong2*)(rp + 2 * C);
            ulonglong2 xc1 = *(const ulonglong2*)(rp + 2 * C + 128);

            float dla = dot_pk(xa0, xa1, wl0, wl1), dga = dot_pk(xa0, xa1, wg0, wg1);
            float dlb = dot_pk(xb0, xb1, wl0, wl1), dgb = dot_pk(xb0, xb1, wg0, wg1);
            float dlc = dot_pk(xc0, xc1, wl0, wl1), dgc = dot_pk(xc0, xc1, wg0, wg1);

            // 6 interleaved butterfly chains
#pragma unroll
            for (int o = 16; o; o >>= 1) {
                dla += __shfl_xor_sync(0xffffffffu, dla, o);
                dga += __shfl_xor_sync(0xffffffffu, dga, o);
                dlb += __shfl_xor_sync(0xffffffffu, dlb, o);
                dgb += __shfl_xor_sync(0xffffffffu, dgb, o);
                dlc += __shfl_xor_sync(0xffffffffu, dlc, o);
                dgc += __shfl_xor_sync(0xffffffffu, dgc, o);
            }
            float ea = __expf(dga + bgv);
            float eb = __expf(dgb + bgv);
            float ec = __expf(dgc + bgv);
            float wra = __fdividef(ea, 1.0f + __expf(-(dla + blv)));
            float wrb = __fdividef(eb, 1.0f + __expf(-(dlb + blv)));
            float wrc = __fdividef(ec, 1.0f + __expf(-(dlc + blv)));
            zacc += ea + eb + ec;
            wacc += wra + wrb + wrc;
            accum_pk(wra, xa0, xa1, s1p, s2p);
            accum_pk(wrb, xb0, xb1, s1p, s2p);
            accum_pk(wrc, xc0, xc1, s1p, s2p);
        } else {
            // ---- slow path: boundary/partial tile ----
#pragma unroll
            for (int j = 0; j < 3; j++) {
                int lr = warp * 3 + j;
                if (lr < rows) {
                    int sv = __ldg(&seg[base + lr]);
                    if (sv != cur) {
                        flush_acc(cur, lane, s1p, s2p, zacc, wacc);
#pragma unroll
                        for (int k = 0; k < 4; k++) { s1p[k] = 0ull; s2p[k] = 0ull; }
                        zacc = 0.f; wacc = 0.f;
                        cur = sv;
                    }
                    const float* rp = tp + lr * C + lane * 4;
                    ulonglong2 x0 = *(const ulonglong2*)(rp);
                    ulonglong2 x1 = *(const ulonglong2*)(rp + 128);
                    float dl = dot_pk(x0, x1, wl0, wl1);
                    float dg = dot_pk(x0, x1, wg0, wg1);
#pragma unroll
                    for (int o = 16; o; o >>= 1) {
                        dl += __shfl_xor_sync(0xffffffffu, dl, o);
                        dg += __shfl_xor_sync(0xffffffffu, dg, o);
                    }
                    float e  = __expf(dg + bgv);
                    float wr = __fdividef(e, 1.0f + __expf(-(dl + blv)));
                    zacc += e;
                    wacc += wr;
                    accum_pk(wr, x0, x1, s1p, s2p);
                }
            }
        }

        __syncthreads();   // all warps done with stage st
        if (tid == 0 && i + DEPTH < nt) {
            int t = t0 + i + DEPTH;
            int rows2 = min(TILE, n - t * TILE);
            uint32_t bytes = (uint32_t)rows2 * C * 4;
            mbar_expect_tx(mb[st], bytes);
            bulk_g2s(tile_s[st], feats + (size_t)t * TILE_FLOATS, bytes, mb[st]);
        }
    }
    flush_acc(cur, lane, s1p, s2p, zacc, wacc);
}

// ---------------------------------------------------------------------------
// finalize: fold 16 segments into mean/rstd, then re-zero accumulators
// ---------------------------------------------------------------------------
__global__ void finalize_kernel() {
    __shared__ float invZ[B];
    __shared__ float invU;
    int t = threadIdx.x;
    if (t < B) invZ[t] = 1.0f / g_Z[t];
    __syncthreads();
    if (t == 0) {
        float U = 0.f;
        for (int b = 0; b < B; b++) U += g_W[b] * invZ[b];
        invU = 1.0f / U;
    }
    __syncthreads();
    float m1 = 0.f, m2 = 0.f;
    for (int b = 0; b < B; b++) {
        m1 += g_S1[b * C + t] * invZ[b];
        m2 += g_S2[b * C + t] * invZ[b];
    }
    float iu = invU;
    m1 *= iu;
    m2 *= iu;
    float var = m2 - m1 * m1;   // sum(weight) == 1 exactly in the math
    g_mean[t] = m1;
    g_rstd[t] = 1.0f / sqrtf(var);
    for (int b = 0; b < B; b++) {
        g_S1[b * C + t] = 0.f;
        g_S2[b * C + t] = 0.f;
    }
    if (t < B) { g_Z[t] = 0.f; g_W[t] = 0.f; }
}

// ---------------------------------------------------------------------------
// pass 2: out = (x - mean[c]) * rstd[c]
// ---------------------------------------------------------------------------
__global__ __launch_bounds__(256)
void normalize_kernel(const float* __restrict__ feats,
                      float* __restrict__ out, int total4)
{
    int base = blockIdx.x * 1024 + threadIdx.x;
    if (base >= total4) return;
    const float4* f4 = (const float4*)feats;
    float4*       o4 = (float4*)out;
    const float4* m4 = (const float4*)g_mean;
    const float4* r4 = (const float4*)g_rstd;

    int cf = base & 63;
    float4 m  = m4[cf];
    float4 rs = r4[cf];

#pragma unroll
    for (int k = 0; k < 4; k++) {
        int i = base + k * 256;
        if (i < total4) {
            float4 x = __ldcs(f4 + i);
            float4 y;
            y.x = (x.x - m.x) * rs.x;
            y.y = (x.y - m.y) * rs.y;
            y.z = (x.z - m.z) * rs.z;
            y.w = (x.w - m.w) * rs.w;
            __stcs(o4 + i, y);
        }
    }
}

// ---------------------------------------------------------------------------
extern "C" void kernel_launch(void* const* d_in, const int* in_sizes, int n_in,
                              void* d_out, int out_size) {
    const float* feats = (const float*)d_in[0];
    const int*   seg   = (const int*)  d_in[1];
    const float* wl    = (const float*)d_in[2];
    const float* bl    = (const float*)d_in[3];
    const float* wg    = (const float*)d_in[4];
    const float* bg    = (const float*)d_in[5];
    float*       out   = (float*)d_out;

    int n = in_sizes[0] / C;

    cudaFuncSetAttribute(pass1_kernel,
                         cudaFuncAttributeMaxDynamicSharedMemorySize, SMEM_BYTES);

    pass1_kernel<<<NBLOCKS, THREADS, SMEM_BYTES>>>(feats, seg, wl, bl, wg, bg, n);

    finalize_kernel<<<1, C>>>();

    int total4 = n * (C / 4);
    normalize_kernel<<<(total4 + 1023) / 1024, 256>>>(feats, out, total4);
}